// round 1
// baseline (speedup 1.0000x reference)
#include <cuda_runtime.h>
#include <math.h>

// ---------------------------------------------------------------------------
// Problem constants
// ---------------------------------------------------------------------------
#define B_  4
#define S_  2048
#define D_  1024
#define H_  16
#define HD_ 64
#define F_  4096
#define E_  8
#define K_  2
#define T_  (B_ * S_)        // 8192 tokens
#define SLOTS_ (T_ * K_)     // 16384 expert slots
#define EPS_ 1e-5f

// ---------------------------------------------------------------------------
// Static device scratch (no allocations allowed)
// ---------------------------------------------------------------------------
__device__ float g_q   [(size_t)T_ * D_];
__device__ float g_k   [(size_t)T_ * D_];
__device__ float g_v   [(size_t)T_ * D_];
__device__ float g_ctx [(size_t)T_ * D_];
__device__ float g_proj[(size_t)T_ * D_];
__device__ float g_x1  [(size_t)T_ * D_];
__device__ float g_scores[(size_t)B_ * H_ * S_ * S_];   // 1.07 GB
__device__ float g_hbuf[(size_t)SLOTS_ * F_];           // 268 MB
__device__ float g_ybuf[(size_t)SLOTS_ * D_];           // 67 MB
__device__ float g_topw[SLOTS_];
__device__ int   g_topi[SLOTS_];
__device__ int   g_slot[SLOTS_];
__device__ int   g_perm[SLOTS_];
__device__ int   g_counts[E_];
__device__ int   g_offsets[E_];
__device__ int   g_cursor[E_];
__device__ float g_sumscore[E_];

__device__ __forceinline__ float gelu_exact(float x) {
    return 0.5f * x * (1.0f + erff(x * 0.70710678118654752f));
}

// ---------------------------------------------------------------------------
// Generic SGEMM: C[M,N] = A[M,K] @ W[K,N] + bias.  BM=BN=128, BK=8, 256 thr.
// M,N multiples of 128; K multiple of 8 (true for all uses here).
// ---------------------------------------------------------------------------
__global__ __launch_bounds__(256) void sgemm_bias(
    const float* __restrict__ A, const float* __restrict__ W,
    const float* __restrict__ bias, float* __restrict__ C,
    int M, int N, int Kd)
{
    __shared__ float As[8][128];
    __shared__ float Bs[8][132];
    const int tid = threadIdx.x;
    const int tx = tid & 15, ty = tid >> 4;
    const int bx = blockIdx.x, by = blockIdx.y;
    const int aRow = tid >> 1, aCol = (tid & 1) * 4;
    const int bRow = tid >> 5, bCol = (tid & 31) * 4;
    const float* Aptr = A + (size_t)(by * 128 + aRow) * Kd + aCol;
    const float* Wptr = W + (size_t)bRow * N + bx * 128 + bCol;

    float acc[8][8];
#pragma unroll
    for (int i = 0; i < 8; i++)
#pragma unroll
        for (int j = 0; j < 8; j++) acc[i][j] = 0.f;

    for (int k0 = 0; k0 < Kd; k0 += 8) {
        float4 av = *(const float4*)(Aptr + k0);
        As[aCol + 0][aRow] = av.x; As[aCol + 1][aRow] = av.y;
        As[aCol + 2][aRow] = av.z; As[aCol + 3][aRow] = av.w;
        *(float4*)&Bs[bRow][bCol] = *(const float4*)(Wptr + (size_t)k0 * N);
        __syncthreads();
#pragma unroll
        for (int kk = 0; kk < 8; kk++) {
            float a[8], b[8];
#pragma unroll
            for (int i = 0; i < 8; i++) a[i] = As[kk][ty * 8 + i];
#pragma unroll
            for (int j = 0; j < 8; j++) b[j] = Bs[kk][tx * 8 + j];
#pragma unroll
            for (int i = 0; i < 8; i++)
#pragma unroll
                for (int j = 0; j < 8; j++) acc[i][j] += a[i] * b[j];
        }
        __syncthreads();
    }
#pragma unroll
    for (int i = 0; i < 8; i++) {
        int r = by * 128 + ty * 8 + i;
        float* crow = C + (size_t)r * N + bx * 128 + tx * 8;
#pragma unroll
        for (int j = 0; j < 8; j++)
            crow[j] = acc[i][j] + bias[bx * 128 + tx * 8 + j];
    }
}

// ---------------------------------------------------------------------------
// Attention scores: scores[bh] = (Q[bh] @ K[bh]^T) / 8.  128x128 tile, HD=64.
// Q,K live in g_q/g_k with [B,S,D] layout, head offset h*64, row stride D.
// ---------------------------------------------------------------------------
__global__ __launch_bounds__(256) void attn_scores_kernel()
{
    __shared__ float Qs[16][132];
    __shared__ float Ks[16][132];
    const int bh = blockIdx.z;
    const int b = bh >> 4, h = bh & 15;
    const float* qb = g_q + (size_t)b * S_ * D_ + h * HD_;
    const float* kb = g_k + (size_t)b * S_ * D_ + h * HD_;
    const int qi0 = blockIdx.y * 128, kj0 = blockIdx.x * 128;
    const int tid = threadIdx.x;
    const int tx = tid & 15, ty = tid >> 4;
    const int lr = tid >> 2, lc = (tid & 3) * 4;

    float acc[8][8];
#pragma unroll
    for (int i = 0; i < 8; i++)
#pragma unroll
        for (int j = 0; j < 8; j++) acc[i][j] = 0.f;

#pragma unroll
    for (int k0 = 0; k0 < HD_; k0 += 16) {
#pragma unroll
        for (int rr = 0; rr < 2; rr++) {
            int row = lr + rr * 64;
            float4 a = *(const float4*)&qb[(size_t)(qi0 + row) * D_ + k0 + lc];
            Qs[lc + 0][row] = a.x; Qs[lc + 1][row] = a.y;
            Qs[lc + 2][row] = a.z; Qs[lc + 3][row] = a.w;
            float4 c = *(const float4*)&kb[(size_t)(kj0 + row) * D_ + k0 + lc];
            Ks[lc + 0][row] = c.x; Ks[lc + 1][row] = c.y;
            Ks[lc + 2][row] = c.z; Ks[lc + 3][row] = c.w;
        }
        __syncthreads();
#pragma unroll
        for (int d = 0; d < 16; d++) {
            float a[8], bb[8];
#pragma unroll
            for (int i = 0; i < 8; i++) a[i]  = Qs[d][ty * 8 + i];
#pragma unroll
            for (int j = 0; j < 8; j++) bb[j] = Ks[d][tx * 8 + j];
#pragma unroll
            for (int i = 0; i < 8; i++)
#pragma unroll
                for (int j = 0; j < 8; j++) acc[i][j] += a[i] * bb[j];
        }
        __syncthreads();
    }
    const float scale = 0.125f;   // 1/sqrt(64)
    const size_t base = (size_t)bh * S_ * S_;
#pragma unroll
    for (int i = 0; i < 8; i++) {
        float* prow = g_scores + base + (size_t)(qi0 + ty * 8 + i) * S_ + kj0 + tx * 8;
#pragma unroll
        for (int j = 0; j < 8; j++) prow[j] = acc[i][j] * scale;
    }
}

// ---------------------------------------------------------------------------
// Row softmax over scores (row length S=2048), in place.
// ---------------------------------------------------------------------------
__global__ __launch_bounds__(256) void softmax_rows_kernel()
{
    const int row = blockIdx.x;
    float* p = g_scores + (size_t)row * S_;
    const int tid = threadIdx.x;
    float v[8];
    float m = -1e30f;
#pragma unroll
    for (int i = 0; i < 8; i++) { v[i] = p[tid + i * 256]; m = fmaxf(m, v[i]); }
    __shared__ float red[256];
    red[tid] = m; __syncthreads();
    for (int s = 128; s > 0; s >>= 1) {
        if (tid < s) red[tid] = fmaxf(red[tid], red[tid + s]);
        __syncthreads();
    }
    m = red[0]; __syncthreads();
    float sum = 0.f;
#pragma unroll
    for (int i = 0; i < 8; i++) { v[i] = __expf(v[i] - m); sum += v[i]; }
    red[tid] = sum; __syncthreads();
    for (int s = 128; s > 0; s >>= 1) {
        if (tid < s) red[tid] += red[tid + s];
        __syncthreads();
    }
    float inv = 1.f / red[0];
#pragma unroll
    for (int i = 0; i < 8; i++) p[tid + i * 256] = v[i] * inv;
}

// ---------------------------------------------------------------------------
// attn @ V: ctx[b,h] = P (SxS) @ V (Sx64).  BM=128, BN=64, BK=16.
// ---------------------------------------------------------------------------
__global__ __launch_bounds__(256) void attn_v_kernel()
{
    __shared__ float Ps[16][132];
    __shared__ float Vs[16][68];
    const int bh = blockIdx.y;
    const int b = bh >> 4, h = bh & 15;
    const int qi0 = blockIdx.x * 128;
    const int tid = threadIdx.x;
    const int tx = tid & 15, ty = tid >> 4;
    const int lr = tid >> 2, lc = (tid & 3) * 4;
    const int vr = tid >> 4, vc = (tid & 15) * 4;
    const size_t sbase = (size_t)bh * S_ * S_;
    const float* vb = g_v + (size_t)b * S_ * D_ + h * HD_;

    float acc[8][4];
#pragma unroll
    for (int i = 0; i < 8; i++)
#pragma unroll
        for (int j = 0; j < 4; j++) acc[i][j] = 0.f;

    for (int k0 = 0; k0 < S_; k0 += 16) {
#pragma unroll
        for (int rr = 0; rr < 2; rr++) {
            int row = lr + rr * 64;
            float4 a = *(const float4*)&g_scores[sbase + (size_t)(qi0 + row) * S_ + k0 + lc];
            Ps[lc + 0][row] = a.x; Ps[lc + 1][row] = a.y;
            Ps[lc + 2][row] = a.z; Ps[lc + 3][row] = a.w;
        }
        *(float4*)&Vs[vr][vc] = *(const float4*)&vb[(size_t)(k0 + vr) * D_ + vc];
        __syncthreads();
#pragma unroll
        for (int d = 0; d < 16; d++) {
            float a[8], bb[4];
#pragma unroll
            for (int i = 0; i < 8; i++) a[i]  = Ps[d][ty * 8 + i];
#pragma unroll
            for (int j = 0; j < 4; j++) bb[j] = Vs[d][tx * 4 + j];
#pragma unroll
            for (int i = 0; i < 8; i++)
#pragma unroll
                for (int j = 0; j < 4; j++) acc[i][j] += a[i] * bb[j];
        }
        __syncthreads();
    }
#pragma unroll
    for (int i = 0; i < 8; i++) {
        float* crow = g_ctx + ((size_t)b * S_ + qi0 + ty * 8 + i) * D_ + h * HD_ + tx * 4;
#pragma unroll
        for (int j = 0; j < 4; j++) crow[j] = acc[i][j];
    }
}

// ---------------------------------------------------------------------------
// LN1: g_x1 = LayerNorm(x + g_proj) * g1 + beta1.  One block per token.
// ---------------------------------------------------------------------------
__global__ __launch_bounds__(256) void add_ln1_kernel(
    const float* __restrict__ x, const float* __restrict__ gamma,
    const float* __restrict__ beta)
{
    const int t = blockIdx.x, tid = threadIdx.x;
    const float* xr = x + (size_t)t * D_;
    const float* pr = g_proj + (size_t)t * D_;
    float v[4]; float s = 0.f, s2 = 0.f;
#pragma unroll
    for (int i = 0; i < 4; i++) {
        int d = tid + i * 256;
        v[i] = xr[d] + pr[d];
        s += v[i]; s2 += v[i] * v[i];
    }
    __shared__ float r1[256], r2[256];
    r1[tid] = s; r2[tid] = s2; __syncthreads();
    for (int st = 128; st > 0; st >>= 1) {
        if (tid < st) { r1[tid] += r1[tid + st]; r2[tid] += r2[tid + st]; }
        __syncthreads();
    }
    float mu = r1[0] * (1.f / D_);
    float var = r2[0] * (1.f / D_) - mu * mu;
    float rstd = rsqrtf(var + EPS_);
    float* o = g_x1 + (size_t)t * D_;
#pragma unroll
    for (int i = 0; i < 4; i++) {
        int d = tid + i * 256;
        o[d] = (v[i] - mu) * rstd * gamma[d] + beta[d];
    }
}

// ---------------------------------------------------------------------------
// Routing: gate logits, softmax, top-2, counts + score sums.
// ---------------------------------------------------------------------------
__global__ void zero_small_kernel()
{
    int i = threadIdx.x;
    if (i < E_) { g_counts[i] = 0; g_sumscore[i] = 0.f; }
}

__global__ __launch_bounds__(256) void gate_kernel(
    const float* __restrict__ gW, const float* __restrict__ gb)
{
    const int t = blockIdx.x, tid = threadIdx.x;
    float acc[E_];
#pragma unroll
    for (int e = 0; e < E_; e++) acc[e] = 0.f;
    const float* xr = g_x1 + (size_t)t * D_;
    for (int d = tid; d < D_; d += 256) {
        float xv = xr[d];
        const float* wr = gW + (size_t)d * E_;
#pragma unroll
        for (int e = 0; e < E_; e++) acc[e] += xv * wr[e];
    }
    __shared__ float red[E_][256];
#pragma unroll
    for (int e = 0; e < E_; e++) red[e][tid] = acc[e];
    __syncthreads();
    for (int st = 128; st > 0; st >>= 1) {
        if (tid < st)
#pragma unroll
            for (int e = 0; e < E_; e++) red[e][tid] += red[e][tid + st];
        __syncthreads();
    }
    if (tid == 0) {
        float lg[E_]; float m = -1e30f;
#pragma unroll
        for (int e = 0; e < E_; e++) { lg[e] = red[e][0] + gb[e]; m = fmaxf(m, lg[e]); }
        float sum = 0.f;
#pragma unroll
        for (int e = 0; e < E_; e++) { lg[e] = __expf(lg[e] - m); sum += lg[e]; }
        float inv = 1.f / sum;
#pragma unroll
        for (int e = 0; e < E_; e++) lg[e] *= inv;
        int i0 = 0;
#pragma unroll
        for (int e = 1; e < E_; e++) if (lg[e] > lg[i0]) i0 = e;
        int i1 = (i0 == 0) ? 1 : 0;
#pragma unroll
        for (int e = 0; e < E_; e++) if (e != i0 && lg[e] > lg[i1]) i1 = e;
        float w0 = lg[i0], w1 = lg[i1], winv = 1.f / (w0 + w1);
        g_topw[2 * t] = w0 * winv; g_topw[2 * t + 1] = w1 * winv;
        g_topi[2 * t] = i0;        g_topi[2 * t + 1] = i1;
        atomicAdd(&g_counts[i0], 1);
        atomicAdd(&g_counts[i1], 1);
#pragma unroll
        for (int e = 0; e < E_; e++) atomicAdd(&g_sumscore[e], lg[e]);
    }
}

__global__ void offsets_kernel(float* auxout)
{
    if (threadIdx.x == 0) {
        int o = 0;
        for (int e = 0; e < E_; e++) {
            g_offsets[e] = o; g_cursor[e] = o; o += g_counts[e];
        }
        float aux = 0.f;
        for (int e = 0; e < E_; e++)
            aux += ((float)g_counts[e] / (float)(T_ * K_)) *
                   (g_sumscore[e] / (float)T_);
        aux *= (float)E_;
        if (auxout) *auxout = aux;
    }
}

__global__ void scatter_kernel()
{
    int t = blockIdx.x * 256 + threadIdx.x;
    if (t >= T_) return;
#pragma unroll
    for (int kk = 0; kk < K_; kk++) {
        int e = g_topi[2 * t + kk];
        int pos = atomicAdd(&g_cursor[e], 1);
        g_perm[pos] = t;
        g_slot[2 * t + kk] = pos;
    }
}

// ---------------------------------------------------------------------------
// MoE GEMM1: h = gelu(x1[perm] @ eW1[e] + eb1[e]).  grid (F/128, 128, E)
// ---------------------------------------------------------------------------
__global__ __launch_bounds__(256) void moe_gemm1_kernel(
    const float* __restrict__ eW1, const float* __restrict__ eb1)
{
    const int e = blockIdx.z;
    const int cnt = g_counts[e];
    const int off = g_offsets[e];
    const int rbase = blockIdx.y * 128;
    if (rbase >= cnt) return;
    __shared__ float As[8][128];
    __shared__ float Bs[8][132];
    const int tid = threadIdx.x;
    const int tx = tid & 15, ty = tid >> 4;
    const int bx = blockIdx.x;
    const int aRow = tid >> 1, aCol = (tid & 1) * 4;
    const int bRow = tid >> 5, bCol = (tid & 31) * 4;
    const int ar = rbase + aRow;
    const int grow = (ar < cnt) ? g_perm[off + ar] : -1;
    const float* Aptr = (grow >= 0) ? (g_x1 + (size_t)grow * D_ + aCol) : g_x1;
    const float* Wptr = eW1 + (size_t)e * D_ * F_ + (size_t)bRow * F_ + bx * 128 + bCol;

    float acc[8][8];
#pragma unroll
    for (int i = 0; i < 8; i++)
#pragma unroll
        for (int j = 0; j < 8; j++) acc[i][j] = 0.f;

    for (int k0 = 0; k0 < D_; k0 += 8) {
        float4 av = (grow >= 0) ? *(const float4*)(Aptr + k0)
                                : make_float4(0.f, 0.f, 0.f, 0.f);
        As[aCol + 0][aRow] = av.x; As[aCol + 1][aRow] = av.y;
        As[aCol + 2][aRow] = av.z; As[aCol + 3][aRow] = av.w;
        *(float4*)&Bs[bRow][bCol] = *(const float4*)(Wptr + (size_t)k0 * F_);
        __syncthreads();
#pragma unroll
        for (int kk = 0; kk < 8; kk++) {
            float a[8], b[8];
#pragma unroll
            for (int i = 0; i < 8; i++) a[i] = As[kk][ty * 8 + i];
#pragma unroll
            for (int j = 0; j < 8; j++) b[j] = Bs[kk][tx * 8 + j];
#pragma unroll
            for (int i = 0; i < 8; i++)
#pragma unroll
                for (int j = 0; j < 8; j++) acc[i][j] += a[i] * b[j];
        }
        __syncthreads();
    }
    const float* be = eb1 + (size_t)e * F_;
#pragma unroll
    for (int i = 0; i < 8; i++) {
        int r = rbase + ty * 8 + i;
        if (r < cnt) {
            float* crow = g_hbuf + (size_t)(off + r) * F_ + bx * 128 + tx * 8;
#pragma unroll
            for (int j = 0; j < 8; j++)
                crow[j] = gelu_exact(acc[i][j] + be[bx * 128 + tx * 8 + j]);
        }
    }
}

// ---------------------------------------------------------------------------
// MoE GEMM2: y = h @ eW2[e] + eb2[e].  grid (D/128, 128, E)
// ---------------------------------------------------------------------------
__global__ __launch_bounds__(256) void moe_gemm2_kernel(
    const float* __restrict__ eW2, const float* __restrict__ eb2)
{
    const int e = blockIdx.z;
    const int cnt = g_counts[e];
    const int off = g_offsets[e];
    const int rbase = blockIdx.y * 128;
    if (rbase >= cnt) return;
    __shared__ float As[8][128];
    __shared__ float Bs[8][132];
    const int tid = threadIdx.x;
    const int tx = tid & 15, ty = tid >> 4;
    const int bx = blockIdx.x;
    const int aRow = tid >> 1, aCol = (tid & 1) * 4;
    const int bRow = tid >> 5, bCol = (tid & 31) * 4;
    const int ar = rbase + aRow;
    const bool avalid = (ar < cnt);
    const float* Aptr = avalid ? (g_hbuf + (size_t)(off + ar) * F_ + aCol) : g_hbuf;
    const float* Wptr = eW2 + (size_t)e * F_ * D_ + (size_t)bRow * D_ + bx * 128 + bCol;

    float acc[8][8];
#pragma unroll
    for (int i = 0; i < 8; i++)
#pragma unroll
        for (int j = 0; j < 8; j++) acc[i][j] = 0.f;

    for (int k0 = 0; k0 < F_; k0 += 8) {
        float4 av = avalid ? *(const float4*)(Aptr + k0)
                           : make_float4(0.f, 0.f, 0.f, 0.f);
        As[aCol + 0][aRow] = av.x; As[aCol + 1][aRow] = av.y;
        As[aCol + 2][aRow] = av.z; As[aCol + 3][aRow] = av.w;
        *(float4*)&Bs[bRow][bCol] = *(const float4*)(Wptr + (size_t)k0 * D_);
        __syncthreads();
#pragma unroll
        for (int kk = 0; kk < 8; kk++) {
            float a[8], b[8];
#pragma unroll
            for (int i = 0; i < 8; i++) a[i] = As[kk][ty * 8 + i];
#pragma unroll
            for (int j = 0; j < 8; j++) b[j] = Bs[kk][tx * 8 + j];
#pragma unroll
            for (int i = 0; i < 8; i++)
#pragma unroll
                for (int j = 0; j < 8; j++) acc[i][j] += a[i] * b[j];
        }
        __syncthreads();
    }
    const float* be = eb2 + (size_t)e * D_;
#pragma unroll
    for (int i = 0; i < 8; i++) {
        int r = rbase + ty * 8 + i;
        if (r < cnt) {
            float* crow = g_ybuf + (size_t)(off + r) * D_ + bx * 128 + tx * 8;
#pragma unroll
            for (int j = 0; j < 8; j++)
                crow[j] = acc[i][j] + be[bx * 128 + tx * 8 + j];
        }
    }
}

// ---------------------------------------------------------------------------
// Combine top-2 expert outputs + residual + LN2 -> final output
// ---------------------------------------------------------------------------
__global__ __launch_bounds__(256) void combine_ln2_kernel(
    const float* __restrict__ gamma, const float* __restrict__ beta,
    float* __restrict__ out)
{
    const int t = blockIdx.x, tid = threadIdx.x;
    const int s0 = g_slot[2 * t], s1 = g_slot[2 * t + 1];
    const float w0 = g_topw[2 * t], w1 = g_topw[2 * t + 1];
    const float* xr = g_x1 + (size_t)t * D_;
    const float* y0 = g_ybuf + (size_t)s0 * D_;
    const float* y1 = g_ybuf + (size_t)s1 * D_;
    float v[4]; float s = 0.f, s2 = 0.f;
#pragma unroll
    for (int i = 0; i < 4; i++) {
        int d = tid + i * 256;
        v[i] = xr[d] + w0 * y0[d] + w1 * y1[d];
        s += v[i]; s2 += v[i] * v[i];
    }
    __shared__ float r1[256], r2[256];
    r1[tid] = s; r2[tid] = s2; __syncthreads();
    for (int st = 128; st > 0; st >>= 1) {
        if (tid < st) { r1[tid] += r1[tid + st]; r2[tid] += r2[tid + st]; }
        __syncthreads();
    }
    float mu = r1[0] * (1.f / D_);
    float var = r2[0] * (1.f / D_) - mu * mu;
    float rstd = rsqrtf(var + EPS_);
    float* o = out + (size_t)t * D_;
#pragma unroll
    for (int i = 0; i < 4; i++) {
        int d = tid + i * 256;
        o[d] = (v[i] - mu) * rstd * gamma[d] + beta[d];
    }
}

// ---------------------------------------------------------------------------
// Host launcher
// ---------------------------------------------------------------------------
extern "C" void kernel_launch(void* const* d_in, const int* in_sizes, int n_in,
                              void* d_out, int out_size)
{
    const float* x     = (const float*)d_in[0];
    const float* Wq    = (const float*)d_in[1];
    const float* bq    = (const float*)d_in[2];
    const float* Wk    = (const float*)d_in[3];
    const float* bk    = (const float*)d_in[4];
    const float* Wv    = (const float*)d_in[5];
    const float* bv    = (const float*)d_in[6];
    const float* Wo    = (const float*)d_in[7];
    const float* bo    = (const float*)d_in[8];
    const float* g1    = (const float*)d_in[9];
    const float* beta1 = (const float*)d_in[10];
    const float* gateW = (const float*)d_in[11];
    const float* gateb = (const float*)d_in[12];
    const float* eW1   = (const float*)d_in[13];
    const float* eb1   = (const float*)d_in[14];
    const float* eW2   = (const float*)d_in[15];
    const float* eb2   = (const float*)d_in[16];
    const float* g2    = (const float*)d_in[17];
    const float* beta2 = (const float*)d_in[18];
    float* out = (float*)d_out;

    float *p_q, *p_k, *p_v, *p_ctx, *p_proj;
    cudaGetSymbolAddress((void**)&p_q,    g_q);
    cudaGetSymbolAddress((void**)&p_k,    g_k);
    cudaGetSymbolAddress((void**)&p_v,    g_v);
    cudaGetSymbolAddress((void**)&p_ctx,  g_ctx);
    cudaGetSymbolAddress((void**)&p_proj, g_proj);

    dim3 gProj(D_ / 128, T_ / 128);                 // (8, 64)
    sgemm_bias<<<gProj, 256>>>(x, Wq, bq, p_q, T_, D_, D_);
    sgemm_bias<<<gProj, 256>>>(x, Wk, bk, p_k, T_, D_, D_);
    sgemm_bias<<<gProj, 256>>>(x, Wv, bv, p_v, T_, D_, D_);

    dim3 gScores(S_ / 128, S_ / 128, B_ * H_);      // (16, 16, 64)
    attn_scores_kernel<<<gScores, 256>>>();

    softmax_rows_kernel<<<B_ * H_ * S_, 256>>>();   // 131072 blocks

    dim3 gAV(S_ / 128, B_ * H_);                    // (16, 64)
    attn_v_kernel<<<gAV, 256>>>();

    sgemm_bias<<<gProj, 256>>>(p_ctx, Wo, bo, p_proj, T_, D_, D_);

    add_ln1_kernel<<<T_, 256>>>(x, g1, beta1);

    zero_small_kernel<<<1, 32>>>();
    gate_kernel<<<T_, 256>>>(gateW, gateb);

    float* auxp = ((size_t)out_size > (size_t)T_ * D_)
                      ? (out + (size_t)T_ * D_) : nullptr;
    offsets_kernel<<<1, 32>>>(auxp);
    scatter_kernel<<<T_ / 256, 256>>>();

    dim3 gM1(F_ / 128, SLOTS_ / 128, E_);           // (32, 128, 8)
    moe_gemm1_kernel<<<gM1, 256>>>(eW1, eb1);
    dim3 gM2(D_ / 128, SLOTS_ / 128, E_);           // (8, 128, 8)
    moe_gemm2_kernel<<<gM2, 256>>>(eW2, eb2);

    combine_ln2_kernel<<<T_, 256>>>(g2, beta2, out);
}

// round 7
// speedup vs baseline: 1.6852x; 1.6852x over previous
#include <cuda_runtime.h>
#include <cuda_bf16.h>
#include <math.h>
#include <stdint.h>

// ---------------------------------------------------------------------------
// Problem constants
// ---------------------------------------------------------------------------
#define B_  4
#define S_  2048
#define D_  1024
#define H_  16
#define HD_ 64
#define F_  4096
#define E_  8
#define K_  2
#define T_  (B_ * S_)        // 8192 tokens
#define SLOTS_ (T_ * K_)     // 16384 expert slots
#define EPS_ 1e-5f
#define K3D_ (3 * D_)        // 3072
#define K3F_ (3 * F_)        // 12288

// tcgen05 only exists in arch-specific ('a') compilation passes.
#if defined(__CUDA_ARCH_FEAT_SM103_ALL) || defined(__CUDA_ARCH_FEAT_SM100_ALL) || defined(__CUDA_ARCH_FEAT_SM101_ALL)
#define HAS_TCGEN05 1
#else
#define HAS_TCGEN05 0
#endif

// ---------------------------------------------------------------------------
// Static device scratch (no allocations allowed)
// ---------------------------------------------------------------------------
__device__ float g_q   [(size_t)T_ * D_];
__device__ float g_k   [(size_t)T_ * D_];
__device__ float g_v   [(size_t)T_ * D_];
__device__ float g_ctx [(size_t)T_ * D_];
__device__ float g_proj[(size_t)T_ * D_];
__device__ float g_x1  [(size_t)T_ * D_];
__device__ float g_scores[(size_t)B_ * H_ * S_ * S_];   // 1.07 GB
__device__ float g_ybuf[(size_t)SLOTS_ * D_];
__device__ float g_topw[SLOTS_];
__device__ int   g_topi[SLOTS_];
__device__ int   g_slot[SLOTS_];
__device__ int   g_perm[SLOTS_];
__device__ int   g_counts[E_];
__device__ int   g_offsets[E_];
__device__ int   g_cursor[E_];
__device__ float g_sumscore[E_];

// bf16 split-3 buffers (A pattern [hi|hi|lo], B pattern [hi|lo|hi])
__device__ __nv_bfloat16 g_x3   [(size_t)T_ * K3D_];
__device__ __nv_bfloat16 g_x13  [(size_t)T_ * K3D_];
__device__ __nv_bfloat16 g_ctx3 [(size_t)T_ * K3D_];
__device__ __nv_bfloat16 g_h3   [(size_t)(SLOTS_ + 128) * K3F_];   // MoE hidden, padded rows
__device__ __nv_bfloat16 g_Wq3T [(size_t)D_ * K3D_];
__device__ __nv_bfloat16 g_Wk3T [(size_t)D_ * K3D_];
__device__ __nv_bfloat16 g_Wv3T [(size_t)D_ * K3D_];
__device__ __nv_bfloat16 g_Wo3T [(size_t)D_ * K3D_];
__device__ __nv_bfloat16 g_eW13T[(size_t)E_ * F_ * K3D_];  // per e: [F rows, 3D]
__device__ __nv_bfloat16 g_eW23T[(size_t)E_ * D_ * K3F_];  // per e: [D rows, 3F]

__device__ __forceinline__ float gelu_exact(float x) {
    return 0.5f * x * (1.0f + erff(x * 0.70710678118654752f));
}

// ---------------------------------------------------------------------------
// PTX helpers
// ---------------------------------------------------------------------------
__device__ __forceinline__ uint32_t smem_u32(const void* p) {
    return (uint32_t)__cvta_generic_to_shared(p);
}

#if HAS_TCGEN05
__device__ __forceinline__ uint64_t make_sw128_desc(uint32_t addr) {
    return ((uint64_t)2 << 61)      // layout SW128
         | ((uint64_t)1 << 46)      // version = 1 (Blackwell)
         | ((uint64_t)64 << 32)     // SBO = 64 (1024B between 8-row groups)
         | ((uint64_t)1 << 16)      // LBO = 1
         | (uint64_t)((addr >> 4) & 0x3FFF);
}

__device__ __forceinline__ void mma_bf16_ss(uint32_t d, uint64_t ad, uint64_t bd,
                                            uint32_t idesc, uint32_t en) {
    asm volatile(
        "{\n\t"
        ".reg .pred p;\n\t"
        "setp.ne.u32 p, %5, 0;\n\t"
        "tcgen05.mma.cta_group::1.kind::f16 [%0], %1, %2, %3, {%4, %4, %4, %4}, p;\n\t"
        "}"
        :: "r"(d), "l"(ad), "l"(bd), "r"(idesc), "r"(0u), "r"(en)
        : "memory");
}

#define LDTM_X32(r, addr) \
    asm volatile( \
        "tcgen05.ld.sync.aligned.32x32b.x32.b32 " \
        "{%0, %1, %2, %3, %4, %5, %6, %7, " \
        " %8, %9, %10, %11, %12, %13, %14, %15, " \
        " %16, %17, %18, %19, %20, %21, %22, %23, " \
        " %24, %25, %26, %27, %28, %29, %30, %31}, [%32];" \
        : "=r"((r)[0]),  "=r"((r)[1]),  "=r"((r)[2]),  "=r"((r)[3]), \
          "=r"((r)[4]),  "=r"((r)[5]),  "=r"((r)[6]),  "=r"((r)[7]), \
          "=r"((r)[8]),  "=r"((r)[9]),  "=r"((r)[10]), "=r"((r)[11]), \
          "=r"((r)[12]), "=r"((r)[13]), "=r"((r)[14]), "=r"((r)[15]), \
          "=r"((r)[16]), "=r"((r)[17]), "=r"((r)[18]), "=r"((r)[19]), \
          "=r"((r)[20]), "=r"((r)[21]), "=r"((r)[22]), "=r"((r)[23]), \
          "=r"((r)[24]), "=r"((r)[25]), "=r"((r)[26]), "=r"((r)[27]), \
          "=r"((r)[28]), "=r"((r)[29]), "=r"((r)[30]), "=r"((r)[31]) \
        : "r"(addr))
#endif // HAS_TCGEN05

__device__ __forceinline__ void mbar_wait(uint32_t addr, uint32_t parity) {
    asm volatile(
        "{\n\t"
        ".reg .pred P1;\n\t"
        "WAIT_LOOP_%=:\n\t"
        "mbarrier.try_wait.parity.acquire.cta.shared::cta.b64 P1, [%0], %1, 0x989680;\n\t"
        "@P1 bra.uni WAIT_DONE_%=;\n\t"
        "bra.uni WAIT_LOOP_%=;\n\t"
        "WAIT_DONE_%=:\n\t"
        "}"
        :: "r"(addr), "r"(parity) : "memory");
}

// legacy warp-MMA helpers (valid from compute_80; used when tcgen05 unavailable)
__device__ __forceinline__ void ldsm_x4(uint32_t* r, uint32_t addr) {
    asm volatile("ldmatrix.sync.aligned.m8n8.x4.shared.b16 {%0,%1,%2,%3}, [%4];"
                 : "=r"(r[0]), "=r"(r[1]), "=r"(r[2]), "=r"(r[3]) : "r"(addr));
}
__device__ __forceinline__ void ldsm_x2(uint32_t* r, uint32_t addr) {
    asm volatile("ldmatrix.sync.aligned.m8n8.x2.shared.b16 {%0,%1}, [%2];"
                 : "=r"(r[0]), "=r"(r[1]) : "r"(addr));
}
__device__ __forceinline__ void mma16816(float* c, const uint32_t* a, const uint32_t* b) {
    asm volatile("mma.sync.aligned.m16n8k16.row.col.f32.bf16.bf16.f32 "
                 "{%0,%1,%2,%3}, {%4,%5,%6,%7}, {%8,%9}, {%0,%1,%2,%3};"
                 : "+f"(c[0]), "+f"(c[1]), "+f"(c[2]), "+f"(c[3])
                 : "r"(a[0]), "r"(a[1]), "r"(a[2]), "r"(a[3]), "r"(b[0]), "r"(b[1]));
}

// Shared epilogue element-writer for all GEMM modes.
// r = local row in 128-tile, gn = global output column.
template<int MODE>
__device__ __forceinline__ void epi_one(
    int r, int gn, float v, const float* __restrict__ bias,
    float* __restrict__ Cout, int Ntot, int by, int rbase, int cnt, int off)
{
    if (MODE == 0) {
        Cout[(size_t)(by * 128 + r) * Ntot + gn] = v + bias[gn];
    } else if (MODE == 1) {
        int rr = rbase + r;
        if (rr < cnt) {
            float hf = gelu_exact(v + bias[gn]);
            __nv_bfloat16 hi = __float2bfloat16(hf);
            __nv_bfloat16 lo = __float2bfloat16(hf - __bfloat162float(hi));
            size_t rb3 = (size_t)(off + rr) * K3F_;
            g_h3[rb3 + gn]          = hi;
            g_h3[rb3 + F_ + gn]     = hi;
            g_h3[rb3 + 2 * F_ + gn] = lo;
        }
    } else {
        int rr = rbase + r;
        if (rr < cnt)
            Cout[(size_t)(off + rr) * Ntot + gn] = v + bias[gn];
    }
}

// ---------------------------------------------------------------------------
// Conversion kernels
// ---------------------------------------------------------------------------
__global__ __launch_bounds__(256) void split3_kernel(
    const float* __restrict__ in, __nv_bfloat16* __restrict__ out, int Kd)
{
    int col = blockIdx.x * 256 + threadIdx.x;
    int row = blockIdx.y;
    float v = in[(size_t)row * Kd + col];
    __nv_bfloat16 hi = __float2bfloat16(v);
    __nv_bfloat16 lo = __float2bfloat16(v - __bfloat162float(hi));
    size_t b = (size_t)row * 3 * Kd;
    out[b + col]          = hi;
    out[b + Kd + col]     = hi;
    out[b + 2 * Kd + col] = lo;
}

__global__ __launch_bounds__(256) void wsplit_kernel(
    const float* __restrict__ W, __nv_bfloat16* __restrict__ out, int Kd, int N)
{
    __shared__ float tile[32][33];
    int z = blockIdx.z;
    const float* Wm = W + (size_t)z * Kd * N;
    __nv_bfloat16* om = out + (size_t)z * N * 3 * Kd;
    int n0 = blockIdx.x * 32, k0 = blockIdx.y * 32;
    int tx = threadIdx.x & 31, tb = threadIdx.x >> 5;
    for (int r = tb; r < 32; r += 8)
        tile[r][tx] = Wm[(size_t)(k0 + r) * N + n0 + tx];
    __syncthreads();
    for (int r = tb; r < 32; r += 8) {
        float v = tile[tx][r];   // W[k0+tx][n0+r]
        __nv_bfloat16 hi = __float2bfloat16(v);
        __nv_bfloat16 lo = __float2bfloat16(v - __bfloat162float(hi));
        size_t base = (size_t)(n0 + r) * 3 * Kd;
        om[base + k0 + tx]          = hi;
        om[base + Kd + k0 + tx]     = lo;
        om[base + 2 * Kd + k0 + tx] = hi;
    }
}

// ---------------------------------------------------------------------------
// Tensor-core GEMM, 128x128 output tile per CTA.
// MODE 0: C = A3[by*128+r]·B3T[n] + bias  (fp32 out)
// MODE 1: MoE GEMM1 (gathered rows, gelu + split-3 store to g_h3)
// MODE 2: MoE GEMM2 (rows off+r, bias -> g_ybuf masked)
// Path A (HAS_TCGEN05): tcgen05 SS bf16 MMA, Kc=64.
// Path B: mma.sync.m16n8k16 bf16 warp MMA, Kc=32.
// ---------------------------------------------------------------------------
template<int MODE>
__global__ __launch_bounds__(256) void tc_gemm(
    const __nv_bfloat16* __restrict__ A3,
    const __nv_bfloat16* __restrict__ B3T,
    const float* __restrict__ bias,
    float* __restrict__ Cout,
    int K3, int Ntot)
{
    __shared__ alignas(1024) char smbuf[32768];
    const int tid = threadIdx.x;
    const int bx = blockIdx.x, by = blockIdx.y, e = blockIdx.z;

    int cnt = 0, off = 0, rbase = 0;
    if (MODE == 1 || MODE == 2) {
        cnt = g_counts[e]; off = g_offsets[e];
        rbase = by * 128;
        if (rbase >= cnt) return;
        B3T  += (size_t)e * Ntot * K3;
        bias += (size_t)e * Ntot;
    }

#if HAS_TCGEN05
    // =================== tcgen05 path ===================
    __shared__ uint32_t s_tmem;
    __shared__ alignas(8) uint64_t s_mbar;

    const uint32_t mbar = smem_u32(&s_mbar);
    if (tid == 0)
        asm volatile("mbarrier.init.shared.b64 [%0], %1;" :: "r"(mbar), "r"(1) : "memory");
    if (tid < 32)
        asm volatile("tcgen05.alloc.cta_group::1.sync.aligned.shared::cta.b32 [%0], %1;"
                     :: "r"(smem_u32(&s_tmem)), "r"(128u) : "memory");
    __syncthreads();
    const uint32_t tmem = s_tmem;

    // per-thread load assignment: 4 (row,seg) pairs for A and B (Kc=64 bf16)
    const __nv_bfloat16* aptr[4];
    const __nv_bfloat16* bptr[4];
    uint32_t swA[4];
#pragma unroll
    for (int j = 0; j < 4; j++) {
        int idx = tid + 256 * j;
        int row = idx >> 3, seg = idx & 7;
        size_t arow;
        if (MODE == 0)      arow = (size_t)(by * 128 + row);
        else if (MODE == 1) { int r = rbase + row; arow = (size_t)((r < cnt) ? g_perm[off + r] : 0); }
        else                arow = (size_t)(off + rbase + row);
        aptr[j] = A3 + arow * K3 + seg * 8;
        bptr[j] = B3T + (size_t)(bx * 128 + row) * K3 + seg * 8;
        uint32_t o = (uint32_t)(row * 128 + seg * 16);
        swA[j] = o ^ ((o >> 3) & 0x70);
    }
    char* smA = smbuf;
    char* smB = smbuf + 16384;
    const uint64_t adesc = make_sw128_desc(smem_u32(smA));
    const uint64_t bdesc = make_sw128_desc(smem_u32(smB));
    const uint32_t idesc = (1u << 4) | (1u << 7) | (1u << 10)
                         | ((128u / 8) << 17) | ((128u / 16) << 24);

    const int nch = K3 >> 6;
    uint4 pa[4], pb[4];
#pragma unroll
    for (int j = 0; j < 4; j++) {
        pa[j] = *(const uint4*)(aptr[j]);
        pb[j] = *(const uint4*)(bptr[j]);
    }
    for (int c = 0; c < nch; c++) {
        if (c > 0) mbar_wait(mbar, (uint32_t)((c - 1) & 1));
#pragma unroll
        for (int j = 0; j < 4; j++) {
            *(uint4*)(smA + swA[j]) = pa[j];
            *(uint4*)(smB + swA[j]) = pb[j];
        }
        asm volatile("fence.proxy.async.shared::cta;" ::: "memory");
        __syncthreads();
        if (tid == 0) {
#pragma unroll
            for (int ks = 0; ks < 4; ks++) {
                uint32_t en = (c > 0 || ks > 0) ? 1u : 0u;
                mma_bf16_ss(tmem, adesc + ks * 2, bdesc + ks * 2, idesc, en);
            }
            asm volatile(
                "tcgen05.commit.cta_group::1.mbarrier::arrive::one.shared::cluster.b64 [%0];"
                :: "r"(mbar) : "memory");
        }
        if (c + 1 < nch) {
#pragma unroll
            for (int j = 0; j < 4; j++) {
                pa[j] = *(const uint4*)(aptr[j] + (c + 1) * 64);
                pb[j] = *(const uint4*)(bptr[j] + (c + 1) * 64);
            }
        }
    }
    mbar_wait(mbar, (uint32_t)((nch - 1) & 1));
    asm volatile("tcgen05.fence::after_thread_sync;" ::: "memory");

    // epilogue: stage 128x32 fp32 through SMEM for coalesced writes
    float* stage = (float*)smbuf;
    for (int cb = 0; cb < 4; cb++) {
        if (tid < 128) {
            uint32_t regs[32];
            LDTM_X32(regs, tmem + cb * 32);
            asm volatile("tcgen05.wait::ld.sync.aligned;" ::: "memory");
#pragma unroll
            for (int cc = 0; cc < 32; cc++)
                stage[tid * 33 + cc] = __uint_as_float(regs[cc]);
        }
        __syncthreads();
        for (int i = tid; i < 128 * 32; i += 256) {
            int r = i >> 5, cc = i & 31;
            int gn = bx * 128 + cb * 32 + cc;
            epi_one<MODE>(r, gn, stage[r * 33 + cc], bias, Cout, Ntot, by, rbase, cnt, off);
        }
        __syncthreads();
    }
    asm volatile("tcgen05.fence::before_thread_sync;" ::: "memory");
    if (tid < 32) {
        asm volatile("tcgen05.relinquish_alloc_permit.cta_group::1.sync.aligned;");
        asm volatile("tcgen05.dealloc.cta_group::1.sync.aligned.b32 %0, %1;"
                     :: "r"(tmem), "r"(128u));
    }
#else
    // =================== mma.sync (legacy HMMA) path ===================
    const int lane = tid & 31, warp = tid >> 5;
    const int wm = warp >> 2, wn = warp & 3;          // 2x4 warp grid: 64x32 per warp
    __nv_bfloat16* As = (__nv_bfloat16*)smbuf;                 // [128][40] (Kc=32 + pad)
    __nv_bfloat16* Bs = (__nv_bfloat16*)(smbuf + 10240);       // [128][40]

    // global load mapping: 2 uint4 (8 bf16) per thread per tile per chunk
    const __nv_bfloat16* aptr[2];
    const __nv_bfloat16* bptr[2];
    int smoff[2];
#pragma unroll
    for (int j = 0; j < 2; j++) {
        int idx = tid + 256 * j;       // 0..511
        int row = idx >> 2, seg = idx & 3;
        size_t arow;
        if (MODE == 0)      arow = (size_t)(by * 128 + row);
        else if (MODE == 1) { int r = rbase + row; arow = (size_t)((r < cnt) ? g_perm[off + r] : 0); }
        else                arow = (size_t)(off + rbase + row);
        aptr[j] = A3 + arow * K3 + seg * 8;
        bptr[j] = B3T + (size_t)(bx * 128 + row) * K3 + seg * 8;
        smoff[j] = row * 40 + seg * 8;
    }

    float acc[4][4][4];
#pragma unroll
    for (int i = 0; i < 4; i++)
#pragma unroll
        for (int j = 0; j < 4; j++)
#pragma unroll
            for (int q = 0; q < 4; q++) acc[i][j][q] = 0.f;

    // ldmatrix per-lane addresses (element offsets precomputed per kk)
    const int a_row = wm * 64 + (lane & 15);
    const int a_k8  = ((lane >> 4) & 1) * 8;
    const int b_row = wn * 32 + (lane & 7);
    const int b_k8  = ((lane >> 3) & 1) * 8;

    const int nch = K3 >> 5;
    uint4 pa[2], pb[2];
#pragma unroll
    for (int j = 0; j < 2; j++) {
        pa[j] = *(const uint4*)(aptr[j]);
        pb[j] = *(const uint4*)(bptr[j]);
    }
    for (int c = 0; c < nch; c++) {
#pragma unroll
        for (int j = 0; j < 2; j++) {
            *(uint4*)(As + smoff[j]) = pa[j];
            *(uint4*)(Bs + smoff[j]) = pb[j];
        }
        __syncthreads();
        if (c + 1 < nch) {
#pragma unroll
            for (int j = 0; j < 2; j++) {
                pa[j] = *(const uint4*)(aptr[j] + (c + 1) * 32);
                pb[j] = *(const uint4*)(bptr[j] + (c + 1) * 32);
            }
        }
#pragma unroll
        for (int kk = 0; kk < 2; kk++) {
            uint32_t bfr[4][2];
#pragma unroll
            for (int j = 0; j < 4; j++)
                ldsm_x2(bfr[j], smem_u32(Bs + (b_row + j * 8) * 40 + kk * 16 + b_k8));
#pragma unroll
            for (int i = 0; i < 4; i++) {
                uint32_t afr[4];
                ldsm_x4(afr, smem_u32(As + (a_row + i * 16) * 40 + kk * 16 + a_k8));
#pragma unroll
                for (int j = 0; j < 4; j++)
                    mma16816(acc[i][j], afr, bfr[j]);
            }
        }
        __syncthreads();
    }

    // epilogue: direct fragment writes
#pragma unroll
    for (int i = 0; i < 4; i++) {
#pragma unroll
        for (int j = 0; j < 4; j++) {
            int rl = wm * 64 + i * 16 + (lane >> 2);
            int cc = bx * 128 + wn * 32 + j * 8 + (lane & 3) * 2;
            epi_one<MODE>(rl,     cc,     acc[i][j][0], bias, Cout, Ntot, by, rbase, cnt, off);
            epi_one<MODE>(rl,     cc + 1, acc[i][j][1], bias, Cout, Ntot, by, rbase, cnt, off);
            epi_one<MODE>(rl + 8, cc,     acc[i][j][2], bias, Cout, Ntot, by, rbase, cnt, off);
            epi_one<MODE>(rl + 8, cc + 1, acc[i][j][3], bias, Cout, Ntot, by, rbase, cnt, off);
        }
    }
#endif
}

// ---------------------------------------------------------------------------
// Attention (SIMT fp32)
// ---------------------------------------------------------------------------
__global__ __launch_bounds__(256) void attn_scores_kernel()
{
    __shared__ float Qs[16][132];
    __shared__ float Ks[16][132];
    const int bh = blockIdx.z;
    const int b = bh >> 4, h = bh & 15;
    const float* qb = g_q + (size_t)b * S_ * D_ + h * HD_;
    const float* kb = g_k + (size_t)b * S_ * D_ + h * HD_;
    const int qi0 = blockIdx.y * 128, kj0 = blockIdx.x * 128;
    const int tid = threadIdx.x;
    const int tx = tid & 15, ty = tid >> 4;
    const int lr = tid >> 2, lc = (tid & 3) * 4;

    float acc[8][8];
#pragma unroll
    for (int i = 0; i < 8; i++)
#pragma unroll
        for (int j = 0; j < 8; j++) acc[i][j] = 0.f;

#pragma unroll
    for (int k0 = 0; k0 < HD_; k0 += 16) {
#pragma unroll
        for (int rr = 0; rr < 2; rr++) {
            int row = lr + rr * 64;
            float4 a = *(const float4*)&qb[(size_t)(qi0 + row) * D_ + k0 + lc];
            Qs[lc + 0][row] = a.x; Qs[lc + 1][row] = a.y;
            Qs[lc + 2][row] = a.z; Qs[lc + 3][row] = a.w;
            float4 c = *(const float4*)&kb[(size_t)(kj0 + row) * D_ + k0 + lc];
            Ks[lc + 0][row] = c.x; Ks[lc + 1][row] = c.y;
            Ks[lc + 2][row] = c.z; Ks[lc + 3][row] = c.w;
        }
        __syncthreads();
#pragma unroll
        for (int d = 0; d < 16; d++) {
            float a[8], bb[8];
#pragma unroll
            for (int i = 0; i < 8; i++) a[i]  = Qs[d][ty * 8 + i];
#pragma unroll
            for (int j = 0; j < 8; j++) bb[j] = Ks[d][tx * 8 + j];
#pragma unroll
            for (int i = 0; i < 8; i++)
#pragma unroll
                for (int j = 0; j < 8; j++) acc[i][j] += a[i] * bb[j];
        }
        __syncthreads();
    }
    const float scale = 0.125f;
    const size_t base = (size_t)bh * S_ * S_;
#pragma unroll
    for (int i = 0; i < 8; i++) {
        float* prow = g_scores + base + (size_t)(qi0 + ty * 8 + i) * S_ + kj0 + tx * 8;
#pragma unroll
        for (int j = 0; j < 8; j++) prow[j] = acc[i][j] * scale;
    }
}

__global__ __launch_bounds__(256) void softmax_rows_kernel()
{
    const int row = blockIdx.x;
    float* p = g_scores + (size_t)row * S_;
    const int tid = threadIdx.x;
    float v[8];
    float m = -1e30f;
#pragma unroll
    for (int i = 0; i < 8; i++) { v[i] = p[tid + i * 256]; m = fmaxf(m, v[i]); }
    __shared__ float red[256];
    red[tid] = m; __syncthreads();
    for (int s = 128; s > 0; s >>= 1) {
        if (tid < s) red[tid] = fmaxf(red[tid], red[tid + s]);
        __syncthreads();
    }
    m = red[0]; __syncthreads();
    float sum = 0.f;
#pragma unroll
    for (int i = 0; i < 8; i++) { v[i] = __expf(v[i] - m); sum += v[i]; }
    red[tid] = sum; __syncthreads();
    for (int s = 128; s > 0; s >>= 1) {
        if (tid < s) red[tid] += red[tid + s];
        __syncthreads();
    }
    float inv = 1.f / red[0];
#pragma unroll
    for (int i = 0; i < 8; i++) p[tid + i * 256] = v[i] * inv;
}

__global__ __launch_bounds__(256) void attn_v_kernel()
{
    __shared__ float Ps[16][132];
    __shared__ float Vs[16][68];
    const int bh = blockIdx.y;
    const int b = bh >> 4, h = bh & 15;
    const int qi0 = blockIdx.x * 128;
    const int tid = threadIdx.x;
    const int tx = tid & 15, ty = tid >> 4;
    const int lr = tid >> 2, lc = (tid & 3) * 4;
    const int vr = tid >> 4, vc = (tid & 15) * 4;
    const size_t sbase = (size_t)bh * S_ * S_;
    const float* vb = g_v + (size_t)b * S_ * D_ + h * HD_;

    float acc[8][4];
#pragma unroll
    for (int i = 0; i < 8; i++)
#pragma unroll
        for (int j = 0; j < 4; j++) acc[i][j] = 0.f;

    for (int k0 = 0; k0 < S_; k0 += 16) {
#pragma unroll
        for (int rr = 0; rr < 2; rr++) {
            int row = lr + rr * 64;
            float4 a = *(const float4*)&g_scores[sbase + (size_t)(qi0 + row) * S_ + k0 + lc];
            Ps[lc + 0][row] = a.x; Ps[lc + 1][row] = a.y;
            Ps[lc + 2][row] = a.z; Ps[lc + 3][row] = a.w;
        }
        *(float4*)&Vs[vr][vc] = *(const float4*)&vb[(size_t)(k0 + vr) * D_ + vc];
        __syncthreads();
#pragma unroll
        for (int d = 0; d < 16; d++) {
            float a[8], bb[4];
#pragma unroll
            for (int i = 0; i < 8; i++) a[i]  = Ps[d][ty * 8 + i];
#pragma unroll
            for (int j = 0; j < 4; j++) bb[j] = Vs[d][tx * 4 + j];
#pragma unroll
            for (int i = 0; i < 8; i++)
#pragma unroll
                for (int j = 0; j < 4; j++) acc[i][j] += a[i] * bb[j];
        }
        __syncthreads();
    }
#pragma unroll
    for (int i = 0; i < 8; i++) {
        float* crow = g_ctx + ((size_t)b * S_ + qi0 + ty * 8 + i) * D_ + h * HD_ + tx * 4;
#pragma unroll
        for (int j = 0; j < 4; j++) crow[j] = acc[i][j];
    }
}

// ---------------------------------------------------------------------------
// LN1 (+ split-3 of x1 for MoE A side)
// ---------------------------------------------------------------------------
__global__ __launch_bounds__(256) void add_ln1_kernel(
    const float* __restrict__ x, const float* __restrict__ gamma,
    const float* __restrict__ beta)
{
    const int t = blockIdx.x, tid = threadIdx.x;
    const float* xr = x + (size_t)t * D_;
    const float* pr = g_proj + (size_t)t * D_;
    float v[4]; float s = 0.f, s2 = 0.f;
#pragma unroll
    for (int i = 0; i < 4; i++) {
        int d = tid + i * 256;
        v[i] = xr[d] + pr[d];
        s += v[i]; s2 += v[i] * v[i];
    }
    __shared__ float r1[256], r2[256];
    r1[tid] = s; r2[tid] = s2; __syncthreads();
    for (int st = 128; st > 0; st >>= 1) {
        if (tid < st) { r1[tid] += r1[tid + st]; r2[tid] += r2[tid + st]; }
        __syncthreads();
    }
    float mu = r1[0] * (1.f / D_);
    float var = r2[0] * (1.f / D_) - mu * mu;
    float rstd = rsqrtf(var + EPS_);
    float* o = g_x1 + (size_t)t * D_;
    size_t b3 = (size_t)t * K3D_;
#pragma unroll
    for (int i = 0; i < 4; i++) {
        int d = tid + i * 256;
        float y = (v[i] - mu) * rstd * gamma[d] + beta[d];
        o[d] = y;
        __nv_bfloat16 hi = __float2bfloat16(y);
        __nv_bfloat16 lo = __float2bfloat16(y - __bfloat162float(hi));
        g_x13[b3 + d]           = hi;
        g_x13[b3 + D_ + d]      = hi;
        g_x13[b3 + 2 * D_ + d]  = lo;
    }
}

// ---------------------------------------------------------------------------
// Routing
// ---------------------------------------------------------------------------
__global__ void zero_small_kernel()
{
    int i = threadIdx.x;
    if (i < E_) { g_counts[i] = 0; g_sumscore[i] = 0.f; }
}

__global__ __launch_bounds__(256) void gate_kernel(
    const float* __restrict__ gW, const float* __restrict__ gb)
{
    const int t = blockIdx.x, tid = threadIdx.x;
    float acc[E_];
#pragma unroll
    for (int e = 0; e < E_; e++) acc[e] = 0.f;
    const float* xr = g_x1 + (size_t)t * D_;
    for (int d = tid; d < D_; d += 256) {
        float xv = xr[d];
        const float* wr = gW + (size_t)d * E_;
#pragma unroll
        for (int e = 0; e < E_; e++) acc[e] += xv * wr[e];
    }
    __shared__ float red[E_][256];
#pragma unroll
    for (int e = 0; e < E_; e++) red[e][tid] = acc[e];
    __syncthreads();
    for (int st = 128; st > 0; st >>= 1) {
        if (tid < st)
#pragma unroll
            for (int e = 0; e < E_; e++) red[e][tid] += red[e][tid + st];
        __syncthreads();
    }
    if (tid == 0) {
        float lg[E_]; float m = -1e30f;
#pragma unroll
        for (int e = 0; e < E_; e++) { lg[e] = red[e][0] + gb[e]; m = fmaxf(m, lg[e]); }
        float sum = 0.f;
#pragma unroll
        for (int e = 0; e < E_; e++) { lg[e] = __expf(lg[e] - m); sum += lg[e]; }
        float inv = 1.f / sum;
#pragma unroll
        for (int e = 0; e < E_; e++) lg[e] *= inv;
        int i0 = 0;
#pragma unroll
        for (int e = 1; e < E_; e++) if (lg[e] > lg[i0]) i0 = e;
        int i1 = (i0 == 0) ? 1 : 0;
#pragma unroll
        for (int e = 0; e < E_; e++) if (e != i0 && lg[e] > lg[i1]) i1 = e;
        float w0 = lg[i0], w1 = lg[i1], winv = 1.f / (w0 + w1);
        g_topw[2 * t] = w0 * winv; g_topw[2 * t + 1] = w1 * winv;
        g_topi[2 * t] = i0;        g_topi[2 * t + 1] = i1;
        atomicAdd(&g_counts[i0], 1);
        atomicAdd(&g_counts[i1], 1);
#pragma unroll
        for (int e = 0; e < E_; e++) atomicAdd(&g_sumscore[e], lg[e]);
    }
}

__global__ void offsets_kernel(float* auxout)
{
    if (threadIdx.x == 0) {
        int o = 0;
        for (int e = 0; e < E_; e++) {
            g_offsets[e] = o; g_cursor[e] = o; o += g_counts[e];
        }
        float aux = 0.f;
        for (int e = 0; e < E_; e++)
            aux += ((float)g_counts[e] / (float)(T_ * K_)) *
                   (g_sumscore[e] / (float)T_);
        aux *= (float)E_;
        if (auxout) *auxout = aux;
    }
}

__global__ void scatter_kernel()
{
    int t = blockIdx.x * 256 + threadIdx.x;
    if (t >= T_) return;
#pragma unroll
    for (int kk = 0; kk < K_; kk++) {
        int e = g_topi[2 * t + kk];
        int pos = atomicAdd(&g_cursor[e], 1);
        g_perm[pos] = t;
        g_slot[2 * t + kk] = pos;
    }
}

// ---------------------------------------------------------------------------
// Combine + LN2
// ---------------------------------------------------------------------------
__global__ __launch_bounds__(256) void combine_ln2_kernel(
    const float* __restrict__ gamma, const float* __restrict__ beta,
    float* __restrict__ out)
{
    const int t = blockIdx.x, tid = threadIdx.x;
    const int s0 = g_slot[2 * t], s1 = g_slot[2 * t + 1];
    const float w0 = g_topw[2 * t], w1 = g_topw[2 * t + 1];
    const float* xr = g_x1 + (size_t)t * D_;
    const float* y0 = g_ybuf + (size_t)s0 * D_;
    const float* y1 = g_ybuf + (size_t)s1 * D_;
    float v[4]; float s = 0.f, s2 = 0.f;
#pragma unroll
    for (int i = 0; i < 4; i++) {
        int d = tid + i * 256;
        v[i] = xr[d] + w0 * y0[d] + w1 * y1[d];
        s += v[i]; s2 += v[i] * v[i];
    }
    __shared__ float r1[256], r2[256];
    r1[tid] = s; r2[tid] = s2; __syncthreads();
    for (int st = 128; st > 0; st >>= 1) {
        if (tid < st) { r1[tid] += r1[tid + st]; r2[tid] += r2[tid + st]; }
        __syncthreads();
    }
    float mu = r1[0] * (1.f / D_);
    float var = r2[0] * (1.f / D_) - mu * mu;
    float rstd = rsqrtf(var + EPS_);
    float* o = out + (size_t)t * D_;
#pragma unroll
    for (int i = 0; i < 4; i++) {
        int d = tid + i * 256;
        o[d] = (v[i] - mu) * rstd * gamma[d] + beta[d];
    }
}

// ---------------------------------------------------------------------------
// Host launcher
// ---------------------------------------------------------------------------
extern "C" void kernel_launch(void* const* d_in, const int* in_sizes, int n_in,
                              void* d_out, int out_size)
{
    const float* x     = (const float*)d_in[0];
    const float* Wq    = (const float*)d_in[1];
    const float* bq    = (const float*)d_in[2];
    const float* Wk    = (const float*)d_in[3];
    const float* bk    = (const float*)d_in[4];
    const float* Wv    = (const float*)d_in[5];
    const float* bv    = (const float*)d_in[6];
    const float* Wo    = (const float*)d_in[7];
    const float* bo    = (const float*)d_in[8];
    const float* g1    = (const float*)d_in[9];
    const float* beta1 = (const float*)d_in[10];
    const float* gateW = (const float*)d_in[11];
    const float* gateb = (const float*)d_in[12];
    const float* eW1   = (const float*)d_in[13];
    const float* eb1   = (const float*)d_in[14];
    const float* eW2   = (const float*)d_in[15];
    const float* eb2   = (const float*)d_in[16];
    const float* g2    = (const float*)d_in[17];
    const float* beta2 = (const float*)d_in[18];
    float* out = (float*)d_out;

    float *p_q, *p_k, *p_v, *p_ctx, *p_proj, *p_ybuf;
    __nv_bfloat16 *p_x3, *p_x13, *p_ctx3, *p_h3;
    __nv_bfloat16 *p_Wq3T, *p_Wk3T, *p_Wv3T, *p_Wo3T, *p_eW13T, *p_eW23T;
    cudaGetSymbolAddress((void**)&p_q,     g_q);
    cudaGetSymbolAddress((void**)&p_k,     g_k);
    cudaGetSymbolAddress((void**)&p_v,     g_v);
    cudaGetSymbolAddress((void**)&p_ctx,   g_ctx);
    cudaGetSymbolAddress((void**)&p_proj,  g_proj);
    cudaGetSymbolAddress((void**)&p_ybuf,  g_ybuf);
    cudaGetSymbolAddress((void**)&p_x3,    g_x3);
    cudaGetSymbolAddress((void**)&p_x13,   g_x13);
    cudaGetSymbolAddress((void**)&p_ctx3,  g_ctx3);
    cudaGetSymbolAddress((void**)&p_h3,    g_h3);
    cudaGetSymbolAddress((void**)&p_Wq3T,  g_Wq3T);
    cudaGetSymbolAddress((void**)&p_Wk3T,  g_Wk3T);
    cudaGetSymbolAddress((void**)&p_Wv3T,  g_Wv3T);
    cudaGetSymbolAddress((void**)&p_Wo3T,  g_Wo3T);
    cudaGetSymbolAddress((void**)&p_eW13T, g_eW13T);
    cudaGetSymbolAddress((void**)&p_eW23T, g_eW23T);

    // ---- conversions ----
    split3_kernel<<<dim3(D_ / 256, T_), 256>>>(x, p_x3, D_);
    wsplit_kernel<<<dim3(D_ / 32, D_ / 32, 1), 256>>>(Wq, p_Wq3T, D_, D_);
    wsplit_kernel<<<dim3(D_ / 32, D_ / 32, 1), 256>>>(Wk, p_Wk3T, D_, D_);
    wsplit_kernel<<<dim3(D_ / 32, D_ / 32, 1), 256>>>(Wv, p_Wv3T, D_, D_);
    wsplit_kernel<<<dim3(D_ / 32, D_ / 32, 1), 256>>>(Wo, p_Wo3T, D_, D_);
    wsplit_kernel<<<dim3(F_ / 32, D_ / 32, E_), 256>>>(eW1, p_eW13T, D_, F_);
    wsplit_kernel<<<dim3(D_ / 32, F_ / 32, E_), 256>>>(eW2, p_eW23T, F_, D_);

    // ---- QKV projections on tensor cores ----
    dim3 gProj(D_ / 128, T_ / 128);                 // (8, 64)
    tc_gemm<0><<<gProj, 256>>>(p_x3, p_Wq3T, bq, p_q, K3D_, D_);
    tc_gemm<0><<<gProj, 256>>>(p_x3, p_Wk3T, bk, p_k, K3D_, D_);
    tc_gemm<0><<<gProj, 256>>>(p_x3, p_Wv3T, bv, p_v, K3D_, D_);

    // ---- attention (SIMT fp32) ----
    dim3 gScores(S_ / 128, S_ / 128, B_ * H_);
    attn_scores_kernel<<<gScores, 256>>>();
    softmax_rows_kernel<<<B_ * H_ * S_, 256>>>();
    dim3 gAV(S_ / 128, B_ * H_);
    attn_v_kernel<<<gAV, 256>>>();

    // ---- O projection ----
    split3_kernel<<<dim3(D_ / 256, T_), 256>>>(p_ctx, p_ctx3, D_);
    tc_gemm<0><<<gProj, 256>>>(p_ctx3, p_Wo3T, bo, p_proj, K3D_, D_);

    add_ln1_kernel<<<T_, 256>>>(x, g1, beta1);

    // ---- routing ----
    zero_small_kernel<<<1, 32>>>();
    gate_kernel<<<T_, 256>>>(gateW, gateb);
    float* auxp = ((size_t)out_size > (size_t)T_ * D_)
                      ? (out + (size_t)T_ * D_) : nullptr;
    offsets_kernel<<<1, 32>>>(auxp);
    scatter_kernel<<<T_ / 256, 256>>>();

    // ---- MoE on tensor cores ----
    dim3 gM1(F_ / 128, SLOTS_ / 128, E_);           // (32, 128, 8)
    tc_gemm<1><<<gM1, 256>>>(p_x13, p_eW13T, eb1, nullptr, K3D_, F_);
    dim3 gM2(D_ / 128, SLOTS_ / 128, E_);           // (8, 128, 8)
    tc_gemm<2><<<gM2, 256>>>(p_h3, p_eW23T, eb2, p_ybuf, K3F_, D_);

    combine_ln2_kernel<<<T_, 256>>>(g2, beta2, out);
}